// round 14
// baseline (speedup 1.0000x reference)
#include <cuda_runtime.h>
#include <cuda_bf16.h>

// DomainGate: T=8192 tokens, E=16 experts, capacity C = ceil(T/E) = 512.
// Output (flattened float32): [ l_aux(1), combine1_sec(T*E*C), dispatch_mask(T*E*C) ]
// combine[t, e, pos] = 1.0 where e = domain_ids[t], pos = # prior active
// same-expert tokens, iff token active (mask=0) and pos < C; all else 0.
// dispatch_mask identical. l_aux = 0.
//
// R13: row-structured fill is pinned at ~6.0 TB/s while memset does ~7.25 on
// the same bytes -> replicate memset's address stream: pure linear aligned
// float4 grid-stride fill, value derived from linear index + g_slot lookup.
// Chain: K_ballot (bitmasks) -> K_rank (popc-prefix -> g_slot) -> K_fill.

#define NTOK 8192
#define NEXP 16
#define CAP  512
#define ROW  (NEXP * CAP)                    // 8192 floats per row
#define COMBINE_ELEMS (NTOK * ROW)           // 67108864
#define TOTAL_F (2 * COMBINE_ELEMS + 1)      // 134217729 floats
#define NVEC (2 * COMBINE_ELEMS / 4)         // 33554432 float4 (covers idx 0..TOTAL_F-2)
#define NGROUP (NTOK / 32)                   // 256 bitmask words per expert

__device__ unsigned int g_bm[NEXP * NGROUP]; // bit j of [e*256+w]: token 32w+j active & expert e
__device__ int          g_eid[NTOK];         // expert id, or -1 if padded
__device__ int          g_slot[NTOK];        // e*CAP+pos, or -1

// ---------------------------------------------------------------------------
// K_ballot: 32 CTAs x 256 threads, one warp per 32-token group.
// ---------------------------------------------------------------------------
__global__ __launch_bounds__(256)
void domain_gate_ballot(const int* __restrict__ domain_ids,
                        const void* __restrict__ mask_raw) {
    __shared__ int byte_mode;

    const int tid  = threadIdx.x;
    const int t    = blockIdx.x * 256 + tid;   // 0..8191
    const int lane = tid & 31;
    const int wgrp = t >> 5;                   // bitmask word index

    // Mask layout detect (int32 vs bytes) over the first 8192 bytes (valid in
    // both layouts; int32 0/1 data has zero upper bytes everywhere).
    if (tid == 0) byte_mode = 0;
    __syncthreads();
    {
        const uint4* m16 = (const uint4*)mask_raw;
        const uint4 a = m16[tid];
        const uint4 b = m16[tid + 256];
        if ((a.x | a.y | a.z | a.w | b.x | b.y | b.z | b.w) & 0xFFFFFF00u)
            byte_mode = 1;
    }
    __syncthreads();

    const int e = domain_ids[t] & 15;
    int padv;
    if (byte_mode) padv = ((const unsigned char*)mask_raw)[t];
    else           padv = ((const int*)mask_raw)[t];
    const bool active = (padv == 0);

    unsigned int my = 0u;
#pragma unroll
    for (int e2 = 0; e2 < NEXP; e2++) {
        const unsigned int b = __ballot_sync(0xFFFFFFFFu, active && (e == e2));
        if (lane == e2) my = b;
    }
    if (lane < NEXP) g_bm[lane * NGROUP + wgrp] = my;

    g_eid[t] = active ? e : -1;
}

// ---------------------------------------------------------------------------
// K_rank: one warp per 4 tokens; popc-prefix of expert bitmask -> g_slot.
// 256 CTAs x 256 threads = 2048 warps.
// ---------------------------------------------------------------------------
__global__ __launch_bounds__(256)
void domain_gate_rank(void) {
    const int lane   = threadIdx.x & 31;
    const int warpId = blockIdx.x * 8 + (threadIdx.x >> 5);   // 0..2047

#pragma unroll
    for (int q = 0; q < 4; q++) {
        const int t = warpId * 4 + q;          // 0..8191
        const int e = g_eid[t];                // uniform broadcast load
        if (e < 0) {
            if (lane == 0) g_slot[t] = -1;
            continue;
        }
        const unsigned int* bm = g_bm + e * NGROUP;
        const int W = t >> 5, R = t & 31;
        int acc = 0;
        for (int i = lane; i < W; i += 32) acc += __popc(bm[i]);
        if (lane == 0 && R) acc += __popc(bm[W] & ((1u << R) - 1u));
        const int pos = __reduce_add_sync(0xFFFFFFFFu, acc);
        if (lane == 0) g_slot[t] = (pos < CAP) ? e * CAP + pos : -1;
    }
}

// ---------------------------------------------------------------------------
// K_fill: memset-pattern linear fill. 8192 CTAs x 256 thr x 16 float4 = NVEC.
// Value of output idx: idx==0 -> 0 (l_aux); else j=idx-1, row (j>>13)&8191,
// r = j&8191, 1.0 iff r == g_slot[row]. g_slot lookup is a warp-uniform L1
// broadcast except at 1-in-2048 row-boundary vectors.
// ---------------------------------------------------------------------------
#define FILL_THREADS 256
#define FILL_CTAS 8192
#define FILL_STRIDE (FILL_CTAS * FILL_THREADS)   // float4s per k-step

__global__ __launch_bounds__(FILL_THREADS, 8)
void domain_gate_fill(float* __restrict__ out) {
    const int gt = blockIdx.x * FILL_THREADS + threadIdx.x;
    float4* __restrict__ o4 = (float4*)out;      // out is 256B aligned

#pragma unroll
    for (int k = 0; k < 16; k++) {
        const int g = gt + k * FILL_STRIDE;      // float4 index, < 2^25
        const int u = (g << 2) - 1;              // j of component .x
        const int r = u & 8191;
        float4 v;
        if (g == 0) {
            const int s0 = g_slot[0];
            v.x = 0.0f;                          // l_aux
            v.y = (0 == s0) ? 1.0f : 0.0f;
            v.z = (1 == s0) ? 1.0f : 0.0f;
            v.w = (2 == s0) ? 1.0f : 0.0f;
        } else if (r <= 8188) {                  // whole vector in one row
            const int s0 = g_slot[(u >> 13) & (NTOK - 1)];
            v.x = (r     == s0) ? 1.0f : 0.0f;
            v.y = (r + 1 == s0) ? 1.0f : 0.0f;
            v.z = (r + 2 == s0) ? 1.0f : 0.0f;
            v.w = (r + 3 == s0) ? 1.0f : 0.0f;
        } else {                                 // crosses a row boundary
            const int tr = u >> 13;
            const int s0 = g_slot[tr & (NTOK - 1)];
            const int s1 = g_slot[(tr + 1) & (NTOK - 1)];
            float* vp = (float*)&v;
#pragma unroll
            for (int c = 0; c < 4; c++) {
                const int rr = r + c;
                vp[c] = (rr <= 8191) ? ((rr == s0) ? 1.0f : 0.0f)
                                     : ((rr - 8192 == s1) ? 1.0f : 0.0f);
            }
        }
        o4[g] = v;
    }

    // Final scalar element (idx TOTAL_F-1): last slot of dmask row 8191.
    if (gt == 0)
        out[TOTAL_F - 1] = (g_slot[NTOK - 1] == ROW - 1) ? 1.0f : 0.0f;
}

extern "C" void kernel_launch(void* const* d_in, const int* in_sizes, int n_in,
                              void* d_out, int out_size) {
    // inputs: [0] input float32 [8192,1024] (unused),
    // [1] domain_ids int32 [8192], [2] mask [8192] (int32 or bytes; auto-detected)
    const int*  domain_ids = (const int*)d_in[1];
    const void* mask       = (const void*)d_in[2];
    float*      out        = (float*)d_out;

    domain_gate_ballot<<<NTOK / 256, 256>>>(domain_ids, mask);
    domain_gate_rank<<<256, 256>>>();
    domain_gate_fill<<<FILL_CTAS, FILL_THREADS>>>(out);
}

// round 16
// speedup vs baseline: 1.0745x; 1.0745x over previous
#include <cuda_runtime.h>
#include <cuda_bf16.h>

// DomainGate: T=8192 tokens, E=16 experts, capacity C = ceil(T/E) = 512.
// Output (flattened float32): [ l_aux(1), combine1_sec(T*E*C), dispatch_mask(T*E*C) ]
// combine[t, e, pos] = 1.0 where e = domain_ids[t], pos = # prior active
// same-expert tokens, iff token active (mask=0) and pos < C; all else 0.
// dispatch_mask identical. l_aux = 0.
//
// R14: R12 structure + PDL. Ballot (5.2us) hides under the fill's zero phase:
// fill zero-stores its row (no dependency), cudaGridDependencySynchronize(),
// then popc-ranks its token and writes the single 1.0. One row per CTA
// (R5's fastest-measured fill config, 76.8us).

#define NTOK 8192
#define NEXP 16
#define CAP  512
#define ROW  (NEXP * CAP)                    // 8192 floats per row
#define COMBINE_ELEMS (NTOK * ROW)           // 67108864
#define NGROUP (NTOK / 32)                   // 256 bitmask words per expert

__device__ unsigned int g_bm[NEXP * NGROUP]; // bit j of [e*256+w]: token 32w+j active & expert e
__device__ int          g_eid[NTOK];         // expert id, or -1 if padded

// ---------------------------------------------------------------------------
// K_ballot: 32 CTAs x 256 threads, one warp per 32-token group.
// ---------------------------------------------------------------------------
__global__ __launch_bounds__(256)
void domain_gate_ballot(const int* __restrict__ domain_ids,
                        const void* __restrict__ mask_raw) {
    __shared__ int byte_mode;

    const int tid  = threadIdx.x;
    const int t    = blockIdx.x * 256 + tid;   // 0..8191
    const int lane = tid & 31;
    const int wgrp = t >> 5;                   // bitmask word index

    // Mask layout detect (int32 vs bytes) over the first 8192 bytes (valid in
    // both layouts; int32 0/1 data has zero upper bytes everywhere).
    if (tid == 0) byte_mode = 0;
    __syncthreads();
    {
        const uint4* m16 = (const uint4*)mask_raw;
        const uint4 a = m16[tid];
        const uint4 b = m16[tid + 256];
        if ((a.x | a.y | a.z | a.w | b.x | b.y | b.z | b.w) & 0xFFFFFF00u)
            byte_mode = 1;
    }
    __syncthreads();

    const int e = domain_ids[t] & 15;
    int padv;
    if (byte_mode) padv = ((const unsigned char*)mask_raw)[t];
    else           padv = ((const int*)mask_raw)[t];
    const bool active = (padv == 0);

    unsigned int my = 0u;
#pragma unroll
    for (int e2 = 0; e2 < NEXP; e2++) {
        const unsigned int b = __ballot_sync(0xFFFFFFFFu, active && (e == e2));
        if (lane == e2) my = b;
    }
    if (lane < NEXP) g_bm[lane * NGROUP + wgrp] = my;

    g_eid[t] = active ? e : -1;
}

// ---------------------------------------------------------------------------
// K_fill: one CTA per output row (16384 rows of 32KB). Zero the row first
// (independent of ballot), then PDL-sync, popc-rank token t, write the 1.0.
// ---------------------------------------------------------------------------
#define FILL_THREADS 256

__global__ __launch_bounds__(FILL_THREADS, 8)
void domain_gate_fill(float* __restrict__ out) {
    __shared__ int sh_part[8];

    const int row = blockIdx.x;              // 0..16383
    const int t   = row & (NTOK - 1);        // token for this row
    const int tid = threadIdx.x;

    float* __restrict__ p = out + 1 + (size_t)row * ROW;

    if (row == 0 && tid == 0) out[0] = 0.0f; // l_aux

    // ---- Phase A: zero the row (no dependency on the ballot kernel).
    // Row starts 4B past 16B alignment: scalar head (0..2) + tail (8191),
    // float4 body over [3, 8191) = 2047 vectors.
    if (tid < 3)  p[tid] = 0.0f;
    if (tid == 3) p[ROW - 1] = 0.0f;

    float4* __restrict__ v = (float4*)(p + 3);
    const float4 z = make_float4(0.f, 0.f, 0.f, 0.f);
#pragma unroll
    for (int k = 0; k < 8; k++) {
        const int idx = tid + k * FILL_THREADS;   // 0..2047
        if (idx < 2047) v[idx] = z;
    }

    // ---- Phase B: wait for ballot grid (PDL), then rank + write the one.
    cudaGridDependencySynchronize();

    const int se = g_eid[t];
    if (se >= 0) {
        const int W = t >> 5, R = t & 31;
        int acc = 0;
        if (tid < W)       acc = __popc(g_bm[se * NGROUP + tid]);
        else if (tid == W) acc = __popc(g_bm[se * NGROUP + W] &
                                        (R ? ((1u << R) - 1u) : 0u));
        acc = __reduce_add_sync(0xFFFFFFFFu, acc);
        if ((tid & 31) == 0) sh_part[tid >> 5] = acc;
    }
    __syncthreads();   // also orders Phase-A zero stores before the 1.0 store

    if (se >= 0 && tid == 0) {
        const int pos = sh_part[0] + sh_part[1] + sh_part[2] + sh_part[3] +
                        sh_part[4] + sh_part[5] + sh_part[6] + sh_part[7];
        if (pos < CAP) p[se * CAP + pos] = 1.0f;   // L2-hit rewrite of one line
    }
}

extern "C" void kernel_launch(void* const* d_in, const int* in_sizes, int n_in,
                              void* d_out, int out_size) {
    // inputs: [0] input float32 [8192,1024] (unused),
    // [1] domain_ids int32 [8192], [2] mask [8192] (int32 or bytes; auto-detected)
    const int*  domain_ids = (const int*)d_in[1];
    const void* mask       = (const void*)d_in[2];
    float*      out        = (float*)d_out;

    domain_gate_ballot<<<NTOK / 256, 256>>>(domain_ids, mask);

    // Fill launched with programmatic stream serialization: its Phase A runs
    // concurrently with the ballot kernel; cudaGridDependencySynchronize()
    // inside gates Phase B on ballot completion.
    cudaLaunchConfig_t cfg = {};
    cfg.gridDim  = dim3(2 * NTOK, 1, 1);
    cfg.blockDim = dim3(FILL_THREADS, 1, 1);
    cudaLaunchAttribute attrs[1];
    attrs[0].id = cudaLaunchAttributeProgrammaticStreamSerialization;
    attrs[0].val.programmaticStreamSerializationAllowed = 1;
    cfg.attrs    = attrs;
    cfg.numAttrs = 1;
    cudaLaunchKernelEx(&cfg, domain_gate_fill, out);
}